// round 1
// baseline (speedup 1.0000x reference)
#include <cuda_runtime.h>

#define N_NODES 100000
#define FEAT    1024
#define OUT_DIM 14
#define N_EDGES 3200000
#define PAD     16            // padded feature width for support/accum scratch

// Scratch (static __device__ globals: no runtime allocation).
__device__ float g_support[N_NODES * PAD];   // 6.4 MB, L2-resident
__device__ float g_accum[N_NODES * PAD];     // 6.4 MB

// ---------------------------------------------------------------------------
// Kernel 1: zero the accumulation scratch (must happen every call; graph replay)
// ---------------------------------------------------------------------------
__global__ void zero_kernel() {
    int i = blockIdx.x * blockDim.x + threadIdx.x;
    const int n4 = N_NODES * PAD / 4;
    if (i < n4) ((float4*)g_accum)[i] = make_float4(0.f, 0.f, 0.f, 0.f);
}

// ---------------------------------------------------------------------------
// Kernel 2: support = x @ W + b, written padded to 16 floats/row.
// Thread-per-row, 128-row tiles, k staged through smem with pad-1 (conflict-free),
// W broadcast from smem, packed f32x2 FMA (2 fp32 FMA per issue slot).
// ---------------------------------------------------------------------------
#define TILE_ROWS 128
#define KC        32

__global__ void __launch_bounds__(TILE_ROWS)
gemm_kernel(const float* __restrict__ x,
            const float* __restrict__ W,
            const float* __restrict__ b)
{
    __shared__ float sx[TILE_ROWS][KC + 1];   // pad-1: bank (t+k)%32, conflict-free
    __shared__ float sw[KC][16];              // W chunk padded to 16 (zeros in 14,15)

    const int t    = threadIdx.x;
    const int row0 = blockIdx.x * TILE_ROWS;
    const int row  = row0 + t;

    unsigned long long acc[7];                // 7 packed f32x2 accumulators = 14 fp32
#pragma unroll
    for (int j = 0; j < 7; j++) acc[j] = 0ULL;

    for (int kc = 0; kc < FEAT; kc += KC) {
        __syncthreads();                      // protect previous chunk's reads
        // Stage x tile [TILE_ROWS x KC], coalesced float4 loads, scalar STS
        // (banks (r + 4*c4 + j) % 32 -> conflict-free within each store).
#pragma unroll
        for (int i = 0; i < KC / 4; i++) {    // 8 float4 per thread
            int f  = t + TILE_ROWS * i;
            int r  = f >> 3;                  // 8 float4 per 128B row-chunk
            int c4 = f & 7;
            int gr = row0 + r;
            float4 v = make_float4(0.f, 0.f, 0.f, 0.f);
            if (gr < N_NODES)
                v = *(const float4*)&x[gr * FEAT + kc + c4 * 4];
            sx[r][c4 * 4 + 0] = v.x;
            sx[r][c4 * 4 + 1] = v.y;
            sx[r][c4 * 4 + 2] = v.z;
            sx[r][c4 * 4 + 3] = v.w;
        }
        // Stage W chunk [KC x 14] into padded [KC x 16]
        for (int idx = t; idx < KC * 16; idx += TILE_ROWS) {
            int k = idx >> 4, j = idx & 15;
            sw[k][j] = (j < OUT_DIM) ? W[(kc + k) * OUT_DIM + j] : 0.0f;
        }
        __syncthreads();

#pragma unroll
        for (int kk = 0; kk < KC; kk++) {
            float xv = sx[t][kk];
            unsigned long long xp;
            asm("mov.b64 %0, {%1, %1};" : "=l"(xp) : "f"(xv));
            // W row: 3x LDS.128 (uniform broadcast) + 1x LDS.64 -> 7 packed pairs
            const ulonglong2* w128 = (const ulonglong2*)&sw[kk][0];
            ulonglong2 wa = w128[0];   // pairs (0,1),(2,3)
            ulonglong2 wb = w128[1];   // pairs (4,5),(6,7)
            ulonglong2 wc = w128[2];   // pairs (8,9),(10,11)
            unsigned long long wd = ((const unsigned long long*)&sw[kk][0])[6]; // (12,13)
            asm("fma.rn.f32x2 %0, %1, %2, %0;" : "+l"(acc[0]) : "l"(xp), "l"(wa.x));
            asm("fma.rn.f32x2 %0, %1, %2, %0;" : "+l"(acc[1]) : "l"(xp), "l"(wa.y));
            asm("fma.rn.f32x2 %0, %1, %2, %0;" : "+l"(acc[2]) : "l"(xp), "l"(wb.x));
            asm("fma.rn.f32x2 %0, %1, %2, %0;" : "+l"(acc[3]) : "l"(xp), "l"(wb.y));
            asm("fma.rn.f32x2 %0, %1, %2, %0;" : "+l"(acc[4]) : "l"(xp), "l"(wc.x));
            asm("fma.rn.f32x2 %0, %1, %2, %0;" : "+l"(acc[5]) : "l"(xp), "l"(wc.y));
            asm("fma.rn.f32x2 %0, %1, %2, %0;" : "+l"(acc[6]) : "l"(xp), "l"(wd));
        }
    }

    if (row < N_NODES) {
        float o[16];
#pragma unroll
        for (int j = 0; j < 7; j++) {
            float lo, hi;
            asm("mov.b64 {%0, %1}, %2;" : "=f"(lo), "=f"(hi) : "l"(acc[j]));
            o[2 * j]     = lo + b[2 * j];
            o[2 * j + 1] = hi + b[2 * j + 1];
        }
        o[14] = 0.f; o[15] = 0.f;
        float4* dst = (float4*)&g_support[row * PAD];
        dst[0] = make_float4(o[0],  o[1],  o[2],  o[3]);
        dst[1] = make_float4(o[4],  o[5],  o[6],  o[7]);
        dst[2] = make_float4(o[8],  o[9],  o[10], o[11]);
        dst[3] = make_float4(o[12], o[13], o[14], o[15]);
    }
}

// ---------------------------------------------------------------------------
// Kernel 3: COO scatter: accum[row] += val * support[col]
// 64B gather per edge (L2 hits) + 4x red.global.add.v4.f32 per edge.
// ---------------------------------------------------------------------------
__global__ void edge_kernel(const float* __restrict__ vals,
                            const int*   __restrict__ erow,
                            const int*   __restrict__ ecol)
{
    int e = blockIdx.x * blockDim.x + threadIdx.x;
    if (e >= N_EDGES) return;
    float v = __ldg(&vals[e]);
    int   r = __ldg(&erow[e]);
    int   c = __ldg(&ecol[e]);

    const float4* s = (const float4*)&g_support[c * PAD];
    float4 s0 = s[0], s1 = s[1], s2 = s[2], s3 = s[3];

    unsigned long long o =
        (unsigned long long)__cvta_generic_to_global(&g_accum[r * PAD]);
    asm volatile("red.global.add.v4.f32 [%0], {%1,%2,%3,%4};" ::
                 "l"(o), "f"(s0.x * v), "f"(s0.y * v), "f"(s0.z * v), "f"(s0.w * v)
                 : "memory");
    asm volatile("red.global.add.v4.f32 [%0], {%1,%2,%3,%4};" ::
                 "l"(o + 16), "f"(s1.x * v), "f"(s1.y * v), "f"(s1.z * v), "f"(s1.w * v)
                 : "memory");
    asm volatile("red.global.add.v4.f32 [%0], {%1,%2,%3,%4};" ::
                 "l"(o + 32), "f"(s2.x * v), "f"(s2.y * v), "f"(s2.z * v), "f"(s2.w * v)
                 : "memory");
    // cols 12,13 real; 14,15 are zero pads (adding v*0 is harmless)
    asm volatile("red.global.add.v4.f32 [%0], {%1,%2,%3,%4};" ::
                 "l"(o + 48), "f"(s3.x * v), "f"(s3.y * v), "f"(s3.z * v), "f"(s3.w * v)
                 : "memory");
}

// ---------------------------------------------------------------------------
// Kernel 4: compact padded accum [N,16] -> output [N,14]
// ---------------------------------------------------------------------------
__global__ void copy_kernel(float* __restrict__ out) {
    int i = blockIdx.x * blockDim.x + threadIdx.x;
    if (i < N_NODES * OUT_DIM) {
        int r = i / OUT_DIM;
        int j = i - r * OUT_DIM;
        out[i] = g_accum[r * PAD + j];
    }
}

// ---------------------------------------------------------------------------
extern "C" void kernel_launch(void* const* d_in, const int* in_sizes, int n_in,
                              void* d_out, int out_size)
{
    const float* x    = (const float*)d_in[0];
    const float* W    = (const float*)d_in[1];
    const float* b    = (const float*)d_in[2];
    const float* vals = (const float*)d_in[3];
    const int*   erow = (const int*)d_in[4];
    const int*   ecol = (const int*)d_in[5];
    float*       out  = (float*)d_out;

    zero_kernel<<<(N_NODES * PAD / 4 + 255) / 256, 256>>>();
    gemm_kernel<<<(N_NODES + TILE_ROWS - 1) / TILE_ROWS, TILE_ROWS>>>(x, W, b);
    edge_kernel<<<(N_EDGES + 255) / 256, 256>>>(vals, erow, ecol);
    copy_kernel<<<(N_NODES * OUT_DIM + 255) / 256, 256>>>(out);
}